// round 1
// baseline (speedup 1.0000x reference)
#include <cuda_runtime.h>

// OpenLSTM: B=4096 independent sequences, T=1024 steps, HID=16, PROJ=2.
// t < 256: teacher-forced (h input = y channels of u_train); t >= 256: h fed back.
//
// Layout: 8 threads per element (each thread owns hidden units g and g+8),
// 4 elements per 32-thread block, 1024 blocks. Weights in registers.
// h projection (16 -> 2) reduced via 3 rounds of shfl.xor within 8-lane groups.

#define T_TOTAL 1024
#define N_CTX   256
#define TPE     8     // threads per element
#define EPB     4     // elements per block (32 threads / 8)

__device__ __forceinline__ float fast_sigmoid(float x) {
    // accurate: 1 / (1 + e^-x); EX2 + RCP on MUFU, ~1e-7 rel err
    float e = __expf(-x);
    return __fdividef(1.0f, 1.0f + e);
}

__device__ __forceinline__ float fast_tanh(float x) {
    // accurate: 1 - 2/(e^{2x}+1); saturates correctly at +-1 on overflow
    float e = __expf(2.0f * x);
    return 1.0f - __fdividef(2.0f, e + 1.0f);
}

__global__ void __launch_bounds__(32)
open_lstm_kernel(const float* __restrict__ u,     // (B, T, 4)
                 const float* __restrict__ w_ih,  // (64, 2)
                 const float* __restrict__ w_hh,  // (64, 2)
                 const float* __restrict__ b_ih,  // (64)
                 const float* __restrict__ b_hh,  // (64)
                 const float* __restrict__ w_hr,  // (2, 16)
                 float* __restrict__ out)         // (B, T, 2)
{
    const int lane = threadIdx.x;          // 0..31
    const int g    = lane & (TPE - 1);     // 0..7, position within element group
    const int e    = blockIdx.x * EPB + (lane >> 3);

    // Per-thread weights: 2 hidden units (j = g, g+8), 4 gate rows each.
    float wi[2][4][2], wh[2][4][2], bb[2][4], wr0[2], wr1[2];
#pragma unroll
    for (int uu = 0; uu < 2; uu++) {
        int j = g + uu * 8;
#pragma unroll
        for (int k = 0; k < 4; k++) {       // gate order: i, f, g, o
            int r = k * 16 + j;
            wi[uu][k][0] = w_ih[r * 2 + 0];
            wi[uu][k][1] = w_ih[r * 2 + 1];
            wh[uu][k][0] = w_hh[r * 2 + 0];
            wh[uu][k][1] = w_hh[r * 2 + 1];
            bb[uu][k]    = b_ih[r] + b_hh[r];
        }
        wr0[uu] = w_hr[j];          // w_hr[0][j]
        wr1[uu] = w_hr[16 + j];     // w_hr[1][j]
    }

    const float4* __restrict__ up = (const float4*)u + (size_t)e * T_TOTAL;
    float2* __restrict__ op       = (float2*)out + (size_t)e * T_TOTAL;

    float c[2] = {0.0f, 0.0f};
    float h0 = 0.0f, h1 = 0.0f;

    float4 v = up[0];
#pragma unroll 1
    for (int t = 0; t < T_TOTAL; t++) {
        // software prefetch of next timestep (clamped)
        float4 vn = up[(t + 1 < T_TOTAL) ? (t + 1) : t];

        const float x0 = v.x, x1 = v.y;
        float hi0, hi1;
        if (t < N_CTX) { hi0 = v.z; hi1 = v.w; }   // teacher forcing
        else           { hi0 = h0;  hi1 = h1; }    // recurrent feedback

        float p0 = 0.0f, p1 = 0.0f;
#pragma unroll
        for (int uu = 0; uu < 2; uu++) {
            float gi = fmaf(wi[uu][0][0], x0, fmaf(wi[uu][0][1], x1,
                       fmaf(wh[uu][0][0], hi0, fmaf(wh[uu][0][1], hi1, bb[uu][0]))));
            float gf = fmaf(wi[uu][1][0], x0, fmaf(wi[uu][1][1], x1,
                       fmaf(wh[uu][1][0], hi0, fmaf(wh[uu][1][1], hi1, bb[uu][1]))));
            float gg = fmaf(wi[uu][2][0], x0, fmaf(wi[uu][2][1], x1,
                       fmaf(wh[uu][2][0], hi0, fmaf(wh[uu][2][1], hi1, bb[uu][2]))));
            float go = fmaf(wi[uu][3][0], x0, fmaf(wi[uu][3][1], x1,
                       fmaf(wh[uu][3][0], hi0, fmaf(wh[uu][3][1], hi1, bb[uu][3]))));

            float si = fast_sigmoid(gi);
            float sf = fast_sigmoid(gf);
            float tg = fast_tanh(gg);
            float so = fast_sigmoid(go);

            c[uu] = fmaf(sf, c[uu], si * tg);
            float s = so * fast_tanh(c[uu]);

            p0 = fmaf(wr0[uu], s, p0);
            p1 = fmaf(wr1[uu], s, p1);
        }

        // reduce partial projections across the 8 lanes of this element
#pragma unroll
        for (int k = 1; k < TPE; k <<= 1) {
            p0 += __shfl_xor_sync(0xffffffffu, p0, k, TPE);
            p1 += __shfl_xor_sync(0xffffffffu, p1, k, TPE);
        }
        h0 = p0;
        h1 = p1;

        if (g == 0) op[t] = make_float2(h0, h1);
        v = vn;
    }
}

extern "C" void kernel_launch(void* const* d_in, const int* in_sizes, int n_in,
                              void* d_out, int out_size)
{
    const float* u    = (const float*)d_in[0];
    const float* w_ih = (const float*)d_in[1];
    const float* w_hh = (const float*)d_in[2];
    const float* b_ih = (const float*)d_in[3];
    const float* b_hh = (const float*)d_in[4];
    const float* w_hr = (const float*)d_in[5];
    float* out = (float*)d_out;

    const int B = in_sizes[0] / (T_TOTAL * 4);   // 4096
    const int grid = B / EPB;                    // 1024 blocks of 32 threads

    open_lstm_kernel<<<grid, 32>>>(u, w_ih, w_hh, b_ih, b_hh, w_hr, out);
}

// round 2
// speedup vs baseline: 1.7139x; 1.7139x over previous
#include <cuda_runtime.h>

// OpenLSTM: B=4096 sequences, T=1024, HID=16, PROJ=2.
// t < 256 teacher-forced; t >= 256 recurrent.
// 8 threads/element (2 hidden units each), 4 elements per 32-thread block,
// 1024 blocks (perfect 148-SM balance). Weights in registers.
//
// R2 changes vs R1 (latency-bound, issue=30%):
//  - MUFU.TANH for tanh AND sigmoid (5 MUFU/unit vs 10, ~40cyc less chain/step)
//  - x-part of gates precomputed from prefetched input (h-chain only 2 FMA deep)
//  - separate teacher-forced loop (no h feedback in chain) unrolled by 2

#define T_TOTAL 1024
#define N_CTX   256
#define TPE     8
#define EPB     4

__device__ __forceinline__ float tanh_fast(float x) {
    float y;
    asm("tanh.approx.f32 %0, %1;" : "=f"(y) : "f"(x));
    return y;
}
__device__ __forceinline__ float sigmoid_fast(float x) {
    // sigma(x) = 0.5*tanh(0.5x) + 0.5   -> 1 MUFU + 2 FMA-pipe ops
    return fmaf(tanh_fast(0.5f * x), 0.5f, 0.5f);
}

__global__ void __launch_bounds__(32)
open_lstm_kernel(const float* __restrict__ u,     // (B, T, 4)
                 const float* __restrict__ w_ih,  // (64, 2)
                 const float* __restrict__ w_hh,  // (64, 2)
                 const float* __restrict__ b_ih,  // (64)
                 const float* __restrict__ b_hh,  // (64)
                 const float* __restrict__ w_hr,  // (2, 16)
                 float* __restrict__ out)         // (B, T, 2)
{
    const int lane = threadIdx.x;
    const int g    = lane & (TPE - 1);
    const int e    = blockIdx.x * EPB + (lane >> 3);

    // Per-thread weights: units j = g and g+8; gate order i,f,g,o.
    float wi[2][4][2], wh[2][4][2], bb[2][4], wr0[2], wr1[2];
#pragma unroll
    for (int uu = 0; uu < 2; uu++) {
        int j = g + uu * 8;
#pragma unroll
        for (int k = 0; k < 4; k++) {
            int r = k * 16 + j;
            wi[uu][k][0] = w_ih[r * 2 + 0];
            wi[uu][k][1] = w_ih[r * 2 + 1];
            wh[uu][k][0] = w_hh[r * 2 + 0];
            wh[uu][k][1] = w_hh[r * 2 + 1];
            bb[uu][k]    = b_ih[r] + b_hh[r];
        }
        wr0[uu] = w_hr[j];
        wr1[uu] = w_hr[16 + j];
    }

    const float4* __restrict__ up = (const float4*)u + (size_t)e * T_TOTAL;
    float2* __restrict__ op       = (float2*)out + (size_t)e * T_TOTAL;

    float c[2] = {0.0f, 0.0f};
    float h0 = 0.0f, h1 = 0.0f;

    float4 v = up[0];
    // x-part of gates for the current step: xp = w_ih @ x + b
    float xp[2][4];
#pragma unroll
    for (int uu = 0; uu < 2; uu++)
#pragma unroll
        for (int k = 0; k < 4; k++)
            xp[uu][k] = fmaf(wi[uu][k][0], v.x, fmaf(wi[uu][k][1], v.y, bb[uu][k]));

    // ---------------- teacher-forced phase: h input comes from data ----------
    // Carried dependency is only the (short) c chain -> pipeline across steps.
#pragma unroll 2
    for (int t = 0; t < N_CTX; t++) {
        float4 vn = up[t + 1];              // t+1 <= 256, always in range
        const float hi0 = v.z, hi1 = v.w;

        float p0 = 0.0f, p1 = 0.0f;
#pragma unroll
        for (int uu = 0; uu < 2; uu++) {
            float gi = fmaf(wh[uu][0][0], hi0, fmaf(wh[uu][0][1], hi1, xp[uu][0]));
            float gf = fmaf(wh[uu][1][0], hi0, fmaf(wh[uu][1][1], hi1, xp[uu][1]));
            float gg = fmaf(wh[uu][2][0], hi0, fmaf(wh[uu][2][1], hi1, xp[uu][2]));
            float go = fmaf(wh[uu][3][0], hi0, fmaf(wh[uu][3][1], hi1, xp[uu][3]));

            float si = sigmoid_fast(gi);
            float sf = sigmoid_fast(gf);
            float tg = tanh_fast(gg);
            float so = sigmoid_fast(go);

            c[uu] = fmaf(sf, c[uu], si * tg);
            float s = so * tanh_fast(c[uu]);

            p0 = fmaf(wr0[uu], s, p0);
            p1 = fmaf(wr1[uu], s, p1);
        }
#pragma unroll
        for (int k = 1; k < TPE; k <<= 1) {
            p0 += __shfl_xor_sync(0xffffffffu, p0, k, TPE);
            p1 += __shfl_xor_sync(0xffffffffu, p1, k, TPE);
        }
        if (g == 0) op[t] = make_float2(p0, p1);
        h0 = p0; h1 = p1;                   // live-out of the phase

        // precompute next step's x-part (independent filler work)
#pragma unroll
        for (int uu = 0; uu < 2; uu++)
#pragma unroll
            for (int k = 0; k < 4; k++)
                xp[uu][k] = fmaf(wi[uu][k][0], vn.x, fmaf(wi[uu][k][1], vn.y, bb[uu][k]));
        v = vn;
    }

    // ---------------- recurrent phase: h feeds back --------------------------
#pragma unroll 1
    for (int t = N_CTX; t < T_TOTAL; t++) {
        float4 vn = up[(t + 1 < T_TOTAL) ? (t + 1) : t];
        const float hi0 = h0, hi1 = h1;

        float p0 = 0.0f, p1 = 0.0f;
#pragma unroll
        for (int uu = 0; uu < 2; uu++) {
            float gi = fmaf(wh[uu][0][0], hi0, fmaf(wh[uu][0][1], hi1, xp[uu][0]));
            float gf = fmaf(wh[uu][1][0], hi0, fmaf(wh[uu][1][1], hi1, xp[uu][1]));
            float gg = fmaf(wh[uu][2][0], hi0, fmaf(wh[uu][2][1], hi1, xp[uu][2]));
            float go = fmaf(wh[uu][3][0], hi0, fmaf(wh[uu][3][1], hi1, xp[uu][3]));

            float si = sigmoid_fast(gi);
            float sf = sigmoid_fast(gf);
            float tg = tanh_fast(gg);
            float so = sigmoid_fast(go);

            c[uu] = fmaf(sf, c[uu], si * tg);
            float s = so * tanh_fast(c[uu]);

            p0 = fmaf(wr0[uu], s, p0);
            p1 = fmaf(wr1[uu], s, p1);
        }
#pragma unroll
        for (int k = 1; k < TPE; k <<= 1) {
            p0 += __shfl_xor_sync(0xffffffffu, p0, k, TPE);
            p1 += __shfl_xor_sync(0xffffffffu, p1, k, TPE);
        }
        h0 = p0; h1 = p1;
        if (g == 0) op[t] = make_float2(h0, h1);

        // next step's x-part: independent of h -> fills shfl/MUFU stall slots
#pragma unroll
        for (int uu = 0; uu < 2; uu++)
#pragma unroll
            for (int k = 0; k < 4; k++)
                xp[uu][k] = fmaf(wi[uu][k][0], vn.x, fmaf(wi[uu][k][1], vn.y, bb[uu][k]));
        v = vn;
    }
}

extern "C" void kernel_launch(void* const* d_in, const int* in_sizes, int n_in,
                              void* d_out, int out_size)
{
    const float* u    = (const float*)d_in[0];
    const float* w_ih = (const float*)d_in[1];
    const float* w_hh = (const float*)d_in[2];
    const float* b_ih = (const float*)d_in[3];
    const float* b_hh = (const float*)d_in[4];
    const float* w_hr = (const float*)d_in[5];
    float* out = (float*)d_out;

    const int B = in_sizes[0] / (T_TOTAL * 4);   // 4096
    const int grid = B / EPB;                    // 1024 blocks x 32 threads

    open_lstm_kernel<<<grid, 32>>>(u, w_ih, w_hh, b_ih, b_hh, w_hr, out);
}